// round 3
// baseline (speedup 1.0000x reference)
#include <cuda_runtime.h>
#include <math.h>

#define BSZ 64
#define SSZ 512
#define ISZ 512
#define HSZ 1024
#define G4  4096

typedef unsigned long long u64;

// Scratch (allocation-free rule: __device__ globals)
__device__ float g_gx[(size_t)SSZ * BSZ * G4];   // [S][B][4H] pre-activations from input transform
__device__ float g_c[BSZ * HSZ];                 // cell state, updated in place each step

// ---------------- packed f32x2 helpers ----------------
__device__ __forceinline__ u64 pack2(float x, float y) {
    u64 r;
    asm("mov.b64 %0, {%1, %2};" : "=l"(r) : "f"(x), "f"(y));
    return r;
}
__device__ __forceinline__ void unpack2(u64 v, float& x, float& y) {
    asm("mov.b64 {%0, %1}, %2;" : "=f"(x), "=f"(y) : "l"(v));
}
__device__ __forceinline__ u64 fma2(u64 a, u64 b, u64 c) {
    u64 d;
    asm("fma.rn.f32x2 %0, %1, %2, %3;" : "=l"(d) : "l"(a), "l"(b), "l"(c));
    return d;
}

// ============================================================================
// Phase A: gx[s*B+b][g] = sum_i x[b][s][i] * w_ih[g][i] + b_ih[g] + b_hh[g]
// Tiled GEMM: M = S*B = 32768, N = 4096, K = 512. 64x64 tile per block, BK=32.
// 256 threads, each computes a 4(m) x 4(n) register tile via f32x2 FMAs.
// ============================================================================
__global__ void __launch_bounds__(256) gx_gemm(
    const float* __restrict__ x,
    const float* __restrict__ wih,
    const float* __restrict__ bih,
    const float* __restrict__ bhh)
{
    __shared__ float Ash[32][68];   // [k][m], padded: 272B row stride (16B aligned)
    __shared__ float Bsh[32][68];   // [k][n]

    const int t  = threadIdx.x;
    const int tx = t & 15;          // n-quad index (n contiguous -> coalesced float4 stores)
    const int ty = t >> 4;          // m-quad index
    const int m0 = blockIdx.y * 64;
    const int n0 = blockIdx.x * 64;

    // Loader mapping: 4 threads per row, 2 float4 per thread
    const int lrow = t >> 2;        // 0..63
    const int lq   = t & 3;         // quad 0..3 (also handles quad+4)

    const int m    = m0 + lrow;     // m = s*B + b
    const int srow = m >> 6;
    const int brow = m & 63;
    const float* xrow = x   + ((size_t)brow * SSZ + srow) * ISZ;
    const float* wrow = wih + (size_t)(n0 + lrow) * ISZ;

    u64 acc[4][2];                  // [m-lane i][n-pair p]
#pragma unroll
    for (int i = 0; i < 4; i++) { acc[i][0] = 0ULL; acc[i][1] = 0ULL; }

    for (int k0 = 0; k0 < ISZ; k0 += 32) {
        float4 a0 = *(const float4*)(xrow + k0 + lq * 4);
        float4 a1 = *(const float4*)(xrow + k0 + lq * 4 + 16);
        float4 b0 = *(const float4*)(wrow + k0 + lq * 4);
        float4 b1 = *(const float4*)(wrow + k0 + lq * 4 + 16);
        __syncthreads();
        Ash[lq*4+0 ][lrow] = a0.x; Ash[lq*4+1 ][lrow] = a0.y;
        Ash[lq*4+2 ][lrow] = a0.z; Ash[lq*4+3 ][lrow] = a0.w;
        Ash[lq*4+16][lrow] = a1.x; Ash[lq*4+17][lrow] = a1.y;
        Ash[lq*4+18][lrow] = a1.z; Ash[lq*4+19][lrow] = a1.w;
        Bsh[lq*4+0 ][lrow] = b0.x; Bsh[lq*4+1 ][lrow] = b0.y;
        Bsh[lq*4+2 ][lrow] = b0.z; Bsh[lq*4+3 ][lrow] = b0.w;
        Bsh[lq*4+16][lrow] = b1.x; Bsh[lq*4+17][lrow] = b1.y;
        Bsh[lq*4+18][lrow] = b1.z; Bsh[lq*4+19][lrow] = b1.w;
        __syncthreads();
#pragma unroll
        for (int kk = 0; kk < 32; kk++) {
            float4 a4 = *(const float4*)&Ash[kk][ty * 4];
            float4 b4 = *(const float4*)&Bsh[kk][tx * 4];
            u64 bn0 = pack2(b4.x, b4.y);
            u64 bn1 = pack2(b4.z, b4.w);
            u64 am;
            am = pack2(a4.x, a4.x); acc[0][0] = fma2(am, bn0, acc[0][0]); acc[0][1] = fma2(am, bn1, acc[0][1]);
            am = pack2(a4.y, a4.y); acc[1][0] = fma2(am, bn0, acc[1][0]); acc[1][1] = fma2(am, bn1, acc[1][1]);
            am = pack2(a4.z, a4.z); acc[2][0] = fma2(am, bn0, acc[2][0]); acc[2][1] = fma2(am, bn1, acc[2][1]);
            am = pack2(a4.w, a4.w); acc[3][0] = fma2(am, bn0, acc[3][0]); acc[3][1] = fma2(am, bn1, acc[3][1]);
        }
    }

    const int nb = n0 + tx * 4;
    float4 bias = make_float4(bih[nb+0] + bhh[nb+0], bih[nb+1] + bhh[nb+1],
                              bih[nb+2] + bhh[nb+2], bih[nb+3] + bhh[nb+3]);
#pragma unroll
    for (int i = 0; i < 4; i++) {
        float l0, h0, l1, h1;
        unpack2(acc[i][0], l0, h0);
        unpack2(acc[i][1], l1, h1);
        float4 v = make_float4(l0 + bias.x, h0 + bias.y, l1 + bias.z, h1 + bias.w);
        *(float4*)&g_gx[(size_t)(m0 + ty * 4 + i) * G4 + nb] = v;
    }
}

// ============================================================================
// Phase B: one fused LSTM step.
// Block bx handles hidden units [8*bx, 8*bx+8) for ALL 4 gates and ALL 64 batches:
// a 64(b) x 32(gate-rows) x 1024(K) GEMM against h_{s-1}, then gate activations
// and the c/h update — all in one kernel (weights read exactly once per step).
// ============================================================================
__global__ void __launch_bounds__(256) lstm_step(
    const float* __restrict__ whh,
    float* out,              // [S][B][H] hidden seq; tail: h_f [B][H], c_f [B][H]
    int s)
{
    __shared__ float Hsh[32][68];    // [k][b]
    __shared__ float Wsh[32][36];    // [k][row]
    __shared__ float Gsh[4][8][65];  // [gate][hh][b] activated gates (padded)

    const int t  = threadIdx.x;
    const int tx = t & 15;           // batch quad: b = 4*tx + bi
    const int ty = t >> 4;           // row pair:   r = 2*ty + rr
    const int n0 = blockIdx.x * 8;   // 8 hidden units per block

    u64 acc[2][2];                   // [b-pair][row rr]
    acc[0][0] = 0ULL; acc[0][1] = 0ULL; acc[1][0] = 0ULL; acc[1][1] = 0ULL;

    if (s > 0) {
        const float* hprev = out + (size_t)(s - 1) * (BSZ * HSZ);

        // Weight loader: 8 threads per row (32 rows), 1 float4 each -> 32 k
        const int lr = t >> 3;       // local row 0..31
        const int lq = t & 7;
        const int gg = lr >> 3;      // gate of this weight row
        const int hh = lr & 7;
        const float* wrow = whh + ((size_t)gg * HSZ + n0 + hh) * HSZ;

        // H loader: 4 threads per batch row, 2 float4 each
        const int hb = t >> 2;       // 0..63
        const int hq = t & 3;
        const float* hrow = hprev + (size_t)hb * HSZ;

        for (int k0 = 0; k0 < HSZ; k0 += 32) {
            float4 h0 = *(const float4*)(hrow + k0 + hq * 4);
            float4 h1 = *(const float4*)(hrow + k0 + hq * 4 + 16);
            float4 wv = *(const float4*)(wrow + k0 + lq * 4);
            __syncthreads();
            Hsh[hq*4+0 ][hb] = h0.x; Hsh[hq*4+1 ][hb] = h0.y;
            Hsh[hq*4+2 ][hb] = h0.z; Hsh[hq*4+3 ][hb] = h0.w;
            Hsh[hq*4+16][hb] = h1.x; Hsh[hq*4+17][hb] = h1.y;
            Hsh[hq*4+18][hb] = h1.z; Hsh[hq*4+19][hb] = h1.w;
            Wsh[lq*4+0][lr] = wv.x;  Wsh[lq*4+1][lr] = wv.y;
            Wsh[lq*4+2][lr] = wv.z;  Wsh[lq*4+3][lr] = wv.w;
            __syncthreads();
#pragma unroll
            for (int kk = 0; kk < 32; kk++) {
                float4 h4 = *(const float4*)&Hsh[kk][tx * 4];
                float2 w2 = *(const float2*)&Wsh[kk][ty * 2];
                u64 hb0 = pack2(h4.x, h4.y);
                u64 hb1 = pack2(h4.z, h4.w);
                u64 wr0 = pack2(w2.x, w2.x);
                u64 wr1 = pack2(w2.y, w2.y);
                acc[0][0] = fma2(hb0, wr0, acc[0][0]);
                acc[1][0] = fma2(hb1, wr0, acc[1][0]);
                acc[0][1] = fma2(hb0, wr1, acc[0][1]);
                acc[1][1] = fma2(hb1, wr1, acc[1][1]);
            }
        }
        __syncthreads();
    }

    // Gate pre-activations -> activations into Gsh
    const float* gxs = g_gx + (size_t)s * (BSZ * G4);
#pragma unroll
    for (int rr = 0; rr < 2; rr++) {
        const int r    = ty * 2 + rr;
        const int gg   = r >> 3;     // 0=i, 1=f, 2=g, 3=o
        const int hh   = r & 7;
        const int grow = gg * HSZ + n0 + hh;
        float l0, h0, l1, h1;
        unpack2(acc[0][rr], l0, h0);
        unpack2(acc[1][rr], l1, h1);
        float av[4] = {l0, h0, l1, h1};
#pragma unroll
        for (int bi = 0; bi < 4; bi++) {
            const int b = tx * 4 + bi;
            float pre = av[bi] + gxs[(size_t)b * G4 + grow];
            float act = (gg == 2) ? tanhf(pre) : 1.0f / (1.0f + expf(-pre));
            Gsh[gg][hh][b] = act;
        }
    }
    __syncthreads();

    // Combine gates -> c, h (one thread per (b, hh); 2 per thread)
    int u = t;
#pragma unroll
    for (int it = 0; it < 2; it++, u += 256) {
        const int b  = u >> 3;
        const int hh = u & 7;
        const int n  = n0 + hh;
        float iv = Gsh[0][hh][b];
        float fv = Gsh[1][hh][b];
        float gv = Gsh[2][hh][b];
        float ov = Gsh[3][hh][b];
        float cp = (s > 0) ? g_c[b * HSZ + n] : 0.0f;
        float cn = fv * cp + iv * gv;
        float hn = ov * tanhf(cn);
        g_c[b * HSZ + n] = cn;
        out[(size_t)s * (BSZ * HSZ) + b * HSZ + n] = hn;
        if (s == SSZ - 1) {
            out[(size_t)SSZ       * (BSZ * HSZ) + b * HSZ + n] = hn;  // h_f
            out[(size_t)(SSZ + 1) * (BSZ * HSZ) + b * HSZ + n] = cn;  // c_f
        }
    }
}

extern "C" void kernel_launch(void* const* d_in, const int* in_sizes, int n_in,
                              void* d_out, int out_size)
{
    const float* x   = (const float*)d_in[0];   // [B,S,I]
    const float* wih = (const float*)d_in[1];   // [4H,I]
    const float* whh = (const float*)d_in[2];   // [4H,H]
    const float* bih = (const float*)d_in[3];   // [4H]
    const float* bhh = (const float*)d_in[4];   // [4H]
    float* out = (float*)d_out;

    // Phase A: input transform for all timesteps (one big GEMM)
    dim3 gridA(G4 / 64, (SSZ * BSZ) / 64);      // (64, 512)
    gx_gemm<<<gridA, 256>>>(x, wih, bih, bhh);

    // Phase B: sequential recurrence, one fused kernel per timestep
    for (int s = 0; s < SSZ; s++) {
        lstm_step<<<HSZ / 8, 256>>>(whh, out, s);
    }
    (void)in_sizes; (void)n_in; (void)out_size;
}

// round 5
// speedup vs baseline: 1.3911x; 1.3911x over previous
#include <cuda_runtime.h>
#include <math.h>

#define BSZ 64
#define SSZ 512
#define ISZ 512
#define HSZ 1024
#define G4  4096
#define KSPLIT 4
#define KCH (HSZ / KSPLIT)   // 256
#define NBLK 128             // persistent grid size (32 row-tiles x 4 k-splits)

typedef unsigned long long u64;

// Scratch (allocation-free rule: __device__ globals)
__device__ float g_gx[(size_t)SSZ * BSZ * G4];      // [S][B][4H] input-transform pre-activations
__device__ float g_part[(size_t)KSPLIT * BSZ * G4]; // [KS][B][4H] split-K partials (reused each step)
__device__ float g_c[BSZ * HSZ];                    // cell state

// Grid barrier state (self-resetting; generation only ever increments)
__device__ unsigned g_bar_count = 0;
__device__ unsigned g_bar_gen   = 0;

// ---------------- packed f32x2 helpers ----------------
__device__ __forceinline__ u64 pack2(float x, float y) {
    u64 r;
    asm("mov.b64 %0, {%1, %2};" : "=l"(r) : "f"(x), "f"(y));
    return r;
}
__device__ __forceinline__ void unpack2(u64 v, float& x, float& y) {
    asm("mov.b64 {%0, %1}, %2;" : "=f"(x), "=f"(y) : "l"(v));
}
__device__ __forceinline__ u64 fma2(u64 a, u64 b, u64 c) {
    u64 d;
    asm("fma.rn.f32x2 %0, %1, %2, %3;" : "=l"(d) : "l"(a), "l"(b), "l"(c));
    return d;
}

// Sense-reversing grid barrier. All NBLK blocks are co-resident (128 blocks,
// 48KB smem, 128 thr -> 1 block/SM on 148 SMs), so spinning cannot deadlock.
__device__ __forceinline__ void grid_barrier() {
    __syncthreads();
    if (threadIdx.x == 0) {
        __threadfence();                                   // release my writes
        unsigned my = *(volatile unsigned*)&g_bar_gen;
        if (atomicAdd(&g_bar_count, 1) == NBLK - 1) {
            atomicExch(&g_bar_count, 0);
            __threadfence();
            *(volatile unsigned*)&g_bar_gen = my + 1;      // open the gate
        } else {
            while (*(volatile unsigned*)&g_bar_gen == my) { }
        }
        __threadfence();                                   // acquire
    }
    __syncthreads();
}

// ============================================================================
// Phase A: gx[m][n] = sum_k x_row(m)[k] * w_ih[n][k] + b_ih[n] + b_hh[n]
// M = S*B = 32768 (m = s*64+b), N = 4096, K = 512.
// 256 threads, tile 128m x 128n, BK=16, double-buffered, 8x8 thread tile (f32x2).
// ============================================================================
__global__ void __launch_bounds__(256) gx_gemm(
    const float* __restrict__ x,
    const float* __restrict__ wih,
    const float* __restrict__ bih,
    const float* __restrict__ bhh)
{
    __shared__ float As[2][16][128];
    __shared__ float Bs[2][16][128];

    const int t  = threadIdx.x;
    const int mt = t & 15;
    const int nt = t >> 4;
    const int n0 = blockIdx.x * 128;
    const int m0 = blockIdx.y * 128;

    const int lr = t >> 1;
    const int lq = (t & 1) * 8;
    const int m  = m0 + lr;
    const float* asrc = x   + ((size_t)(m & 63) * SSZ + (m >> 6)) * ISZ + lq;
    const float* bsrc = wih + (size_t)(n0 + lr) * ISZ + lq;

    u64 acc[4][8];
#pragma unroll
    for (int p = 0; p < 4; p++)
#pragma unroll
        for (int j = 0; j < 8; j++) acc[p][j] = 0ULL;

    float4 ab[2], bb[2];
#pragma unroll
    for (int q = 0; q < 2; q++) {
        ab[q] = *(const float4*)(asrc + q * 4);
        bb[q] = *(const float4*)(bsrc + q * 4);
    }
#pragma unroll
    for (int q = 0; q < 2; q++) {
        As[0][lq + q*4 + 0][lr] = ab[q].x; As[0][lq + q*4 + 1][lr] = ab[q].y;
        As[0][lq + q*4 + 2][lr] = ab[q].z; As[0][lq + q*4 + 3][lr] = ab[q].w;
        Bs[0][lq + q*4 + 0][lr] = bb[q].x; Bs[0][lq + q*4 + 1][lr] = bb[q].y;
        Bs[0][lq + q*4 + 2][lr] = bb[q].z; Bs[0][lq + q*4 + 3][lr] = bb[q].w;
    }
    __syncthreads();

    const int NTILES = ISZ / 16;
    for (int tile = 0; tile < NTILES; tile++) {
        const int st = tile & 1;
        if (tile + 1 < NTILES) {
#pragma unroll
            for (int q = 0; q < 2; q++) {
                ab[q] = *(const float4*)(asrc + (tile + 1) * 16 + q * 4);
                bb[q] = *(const float4*)(bsrc + (tile + 1) * 16 + q * 4);
            }
        }
#pragma unroll
        for (int kk = 0; kk < 16; kk++) {
            ulonglong2 m01 = *(const ulonglong2*)&As[st][kk][mt * 8];
            ulonglong2 m23 = *(const ulonglong2*)&As[st][kk][mt * 8 + 4];
            float4 v0 = *(const float4*)&Bs[st][kk][nt * 8];
            float4 v1 = *(const float4*)&Bs[st][kk][nt * 8 + 4];
            u64 hp[4] = {m01.x, m01.y, m23.x, m23.y};
            float nv[8] = {v0.x, v0.y, v0.z, v0.w, v1.x, v1.y, v1.z, v1.w};
#pragma unroll
            for (int j = 0; j < 8; j++) {
                u64 wd = pack2(nv[j], nv[j]);
#pragma unroll
                for (int p = 0; p < 4; p++) acc[p][j] = fma2(hp[p], wd, acc[p][j]);
            }
        }
        if (tile + 1 < NTILES) {
            const int so = st ^ 1;
#pragma unroll
            for (int q = 0; q < 2; q++) {
                As[so][lq + q*4 + 0][lr] = ab[q].x; As[so][lq + q*4 + 1][lr] = ab[q].y;
                As[so][lq + q*4 + 2][lr] = ab[q].z; As[so][lq + q*4 + 3][lr] = ab[q].w;
                Bs[so][lq + q*4 + 0][lr] = bb[q].x; Bs[so][lq + q*4 + 1][lr] = bb[q].y;
                Bs[so][lq + q*4 + 2][lr] = bb[q].z; Bs[so][lq + q*4 + 3][lr] = bb[q].w;
            }
        }
        __syncthreads();
    }

    const int nb = n0 + nt * 8;
    float4 bi0 = *(const float4*)&bih[nb];
    float4 bi1 = *(const float4*)&bih[nb + 4];
    float4 bh0 = *(const float4*)&bhh[nb];
    float4 bh1 = *(const float4*)&bhh[nb + 4];
    float bias[8] = {bi0.x + bh0.x, bi0.y + bh0.y, bi0.z + bh0.z, bi0.w + bh0.w,
                     bi1.x + bh1.x, bi1.y + bh1.y, bi1.z + bh1.z, bi1.w + bh1.w};
#pragma unroll
    for (int p = 0; p < 4; p++) {
        float lo[8], hi[8];
#pragma unroll
        for (int j = 0; j < 8; j++) unpack2(acc[p][j], lo[j], hi[j]);
        const int mrow = m0 + mt * 8 + p * 2;
        float* d0 = &g_gx[(size_t)mrow * G4 + nb];
        *(float4*)d0       = make_float4(lo[0]+bias[0], lo[1]+bias[1], lo[2]+bias[2], lo[3]+bias[3]);
        *(float4*)(d0 + 4) = make_float4(lo[4]+bias[4], lo[5]+bias[5], lo[6]+bias[6], lo[7]+bias[7]);
        float* d1 = d0 + G4;
        *(float4*)d1       = make_float4(hi[0]+bias[0], hi[1]+bias[1], hi[2]+bias[2], hi[3]+bias[3]);
        *(float4*)(d1 + 4) = make_float4(hi[4]+bias[4], hi[5]+bias[5], hi[6]+bias[6], hi[7]+bias[7]);
    }
}

// ============================================================================
// Persistent recurrence: ONE launch runs all 512 timesteps.
// Per step: split-K GEMM partials (64b x 128r x 256k per block), grid barrier,
// distributed combine (gates + c/h update), grid barrier.
// Cross-SM re-read buffers (h_prev, g_part) are read via __ldcg (L2 path).
// ============================================================================
__global__ void __launch_bounds__(128) lstm_persist(
    const float* __restrict__ whh,
    float* out)
{
    __shared__ float Hs[2][32][64];     // [stage][k][b]
    __shared__ float Ws[2][32][128];    // [stage][k][r]

    const int t  = threadIdx.x;
    const int bt = t & 7;               // 8 b-groups of 8
    const int rt = t >> 3;              // 16 r-groups of 8
    const int rtile = blockIdx.x >> 2;  // 0..31
    const int ks    = blockIdx.x & 3;   // 0..3
    const int r0    = rtile * 128;
    const int kbase = ks * KCH;

    // Loader-invariant addresses
    const int hb = t >> 1;              // 0..63
    const int hq = (t & 1) * 16;        // k offset 0/16
    const float* wsrc = whh + (size_t)(r0 + t) * HSZ + kbase;

    // Combine slice for this block: 512 consecutive (b,n) elements
    const int ebase = blockIdx.x * 512;

    for (int s = 0; s < SSZ; s++) {
        if (s > 0) {
            const float* hprev = out + (size_t)(s - 1) * (BSZ * HSZ);
            const float* hsrc  = hprev + (size_t)hb * HSZ + kbase + hq;

            u64 acc[4][8];
#pragma unroll
            for (int p = 0; p < 4; p++)
#pragma unroll
                for (int j = 0; j < 8; j++) acc[p][j] = 0ULL;

            float4 hbuf[4], wbuf[8];
#pragma unroll
            for (int q = 0; q < 4; q++) hbuf[q] = __ldcg((const float4*)(hsrc + q * 4));
#pragma unroll
            for (int q = 0; q < 8; q++) wbuf[q] = *(const float4*)(wsrc + q * 4);
#pragma unroll
            for (int q = 0; q < 4; q++) {
                Hs[0][hq + q*4 + 0][hb] = hbuf[q].x; Hs[0][hq + q*4 + 1][hb] = hbuf[q].y;
                Hs[0][hq + q*4 + 2][hb] = hbuf[q].z; Hs[0][hq + q*4 + 3][hb] = hbuf[q].w;
            }
#pragma unroll
            for (int q = 0; q < 8; q++) {
                Ws[0][q*4 + 0][t] = wbuf[q].x; Ws[0][q*4 + 1][t] = wbuf[q].y;
                Ws[0][q*4 + 2][t] = wbuf[q].z; Ws[0][q*4 + 3][t] = wbuf[q].w;
            }
            __syncthreads();

            const int NTILES = KCH / 32;    // 8
            for (int tile = 0; tile < NTILES; tile++) {
                const int st = tile & 1;
                if (tile + 1 < NTILES) {
#pragma unroll
                    for (int q = 0; q < 4; q++)
                        hbuf[q] = __ldcg((const float4*)(hsrc + (tile+1)*32 + q*4));
#pragma unroll
                    for (int q = 0; q < 8; q++)
                        wbuf[q] = *(const float4*)(wsrc + (tile+1)*32 + q*4);
                }
#pragma unroll
                for (int kk = 0; kk < 32; kk++) {
                    ulonglong2 h01 = *(const ulonglong2*)&Hs[st][kk][bt * 8];
                    ulonglong2 h23 = *(const ulonglong2*)&Hs[st][kk][bt * 8 + 4];
                    float4 w0 = *(const float4*)&Ws[st][kk][rt * 8];
                    float4 w1 = *(const float4*)&Ws[st][kk][rt * 8 + 4];
                    u64 hp[4] = {h01.x, h01.y, h23.x, h23.y};
                    float wv[8] = {w0.x, w0.y, w0.z, w0.w, w1.x, w1.y, w1.z, w1.w};
#pragma unroll
                    for (int j = 0; j < 8; j++) {
                        u64 wd = pack2(wv[j], wv[j]);
#pragma unroll
                        for (int p = 0; p < 4; p++) acc[p][j] = fma2(hp[p], wd, acc[p][j]);
                    }
                }
                if (tile + 1 < NTILES) {
                    const int so = st ^ 1;
#pragma unroll
                    for (int q = 0; q < 4; q++) {
                        Hs[so][hq + q*4 + 0][hb] = hbuf[q].x; Hs[so][hq + q*4 + 1][hb] = hbuf[q].y;
                        Hs[so][hq + q*4 + 2][hb] = hbuf[q].z; Hs[so][hq + q*4 + 3][hb] = hbuf[q].w;
                    }
#pragma unroll
                    for (int q = 0; q < 8; q++) {
                        Ws[so][q*4 + 0][t] = wbuf[q].x; Ws[so][q*4 + 1][t] = wbuf[q].y;
                        Ws[so][q*4 + 2][t] = wbuf[q].z; Ws[so][q*4 + 3][t] = wbuf[q].w;
                    }
                }
                __syncthreads();
            }

            // Store partials [ks][b][r]
            const int rb = r0 + rt * 8;
#pragma unroll
            for (int p = 0; p < 4; p++) {
                float lo[8], hi[8];
#pragma unroll
                for (int j = 0; j < 8; j++) unpack2(acc[p][j], lo[j], hi[j]);
                const int b = bt * 8 + p * 2;
                float* d0 = &g_part[((size_t)ks * BSZ + b) * G4 + rb];
                *(float4*)d0       = make_float4(lo[0], lo[1], lo[2], lo[3]);
                *(float4*)(d0 + 4) = make_float4(lo[4], lo[5], lo[6], lo[7]);
                float* d1 = d0 + G4;
                *(float4*)d1       = make_float4(hi[0], hi[1], hi[2], hi[3]);
                *(float4*)(d1 + 4) = make_float4(hi[4], hi[5], hi[6], hi[7]);
            }
        }

        grid_barrier();   // partials visible -> combine

        // Distributed combine: this block handles elements [ebase, ebase+512)
        const float* gxs = g_gx + (size_t)s * (BSZ * G4);
#pragma unroll
        for (int i = t; i < 512; i += 128) {
            const int e = ebase + i;
            const int b = e >> 10;
            const int n = e & 1023;
            float pre[4];
#pragma unroll
            for (int g = 0; g < 4; g++) {
                const int r = g * HSZ + n;
                float v = gxs[(size_t)b * G4 + r];
                if (s > 0) {
#pragma unroll
                    for (int kp = 0; kp < KSPLIT; kp++)
                        v += __ldcg(&g_part[((size_t)kp * BSZ + b) * G4 + r]);
                }
                pre[g] = v;
            }
            const float iv = 1.0f / (1.0f + expf(-pre[0]));
            const float fv = 1.0f / (1.0f + expf(-pre[1]));
            const float gv = tanhf(pre[2]);
            const float ov = 1.0f / (1.0f + expf(-pre[3]));
            const float cp = (s > 0) ? g_c[b * HSZ + n] : 0.0f;
            const float cn = fv * cp + iv * gv;
            const float hn = ov * tanhf(cn);
            g_c[b * HSZ + n] = cn;
            out[((size_t)s * BSZ + b) * HSZ + n] = hn;
            if (s == SSZ - 1) {
                out[((size_t)SSZ       * BSZ + b) * HSZ + n] = hn;  // h_f
                out[((size_t)(SSZ + 1) * BSZ + b) * HSZ + n] = cn;  // c_f
            }
        }

        grid_barrier();   // h(s) visible -> next step's GEMM
    }
}

extern "C" void kernel_launch(void* const* d_in, const int* in_sizes, int n_in,
                              void* d_out, int out_size)
{
    const float* x   = (const float*)d_in[0];   // [B,S,I]
    const float* wih = (const float*)d_in[1];   // [4H,I]
    const float* whh = (const float*)d_in[2];   // [4H,H]
    const float* bih = (const float*)d_in[3];   // [4H]
    const float* bhh = (const float*)d_in[4];   // [4H]
    float* out = (float*)d_out;

    // Phase A: input transform for all timesteps
    dim3 gridA(G4 / 128, (SSZ * BSZ) / 128);    // (32, 256)
    gx_gemm<<<gridA, 256>>>(x, wih, bih, bhh);

    // Phase B: entire recurrence in one persistent launch (graph = 2 nodes)
    lstm_persist<<<NBLK, 128>>>(whh, out);

    (void)in_sizes; (void)n_in; (void)out_size;
}